// round 7
// baseline (speedup 1.0000x reference)
#include <cuda_runtime.h>
#include <cuda_bf16.h>

// DeformableConvLayer: B=4, H=W=256, C=64, K=3x3, UNITS=1.
//   Phase 1: P_k[pix] = <input[pix,:], kern[k,:]> (dense streaming contraction);
//            64 of its blocks also warp-ballot-pack the {0,1} mask into 8KB of bits.
//   Phase 2: out = bias + sum_k (diff ? P_k@offset : P_k@base). Mask tests are
//            smem bit-tests (no scattered global mask gathers); the offset-path
//            P gather is predicated on diff (~50% of lanes), base path comes from
//            coalesced smem rows. Kills the L1 wavefront-replay wall.

namespace {

constexpr int Hc = 256;
constexpr int Wc = 256;
constexpr int PIX = 4 * Hc * Wc;               // 262144

__device__ float    g_P[9 * PIX];              // 9.4 MB tap-plane scratch
__device__ unsigned g_maskbits[2048];          // 256x256 mask, 1 bit/px (8 KB)

__device__ __forceinline__ unsigned long long fma2(unsigned long long a,
                                                   unsigned long long b,
                                                   unsigned long long c)
{
    unsigned long long d;
    asm("fma.rn.f32x2 %0, %1, %2, %3;" : "=l"(d) : "l"(a), "l"(b), "l"(c));
    return d;
}

// ---------------- Phase 1: contraction + mask bit-pack ----------------
constexpr int P1_T = 128;

__global__ __launch_bounds__(P1_T)
void dcn_phase1(const float* __restrict__ input,   // [PIX, 64]
                const float* __restrict__ kern,    // [9, 64]
                const float* __restrict__ mask)    // [256,256]
{
    __shared__ float4 in_s[P1_T * 8];    // 16 KB, [pixel][c4 ^ (pixel&7)]
    __shared__ float4 w_s[9 * 16];

    const int t = threadIdx.x;
    const int pixbase = blockIdx.x * P1_T;

    // First 64 blocks also pack the mask: 1024 floats/block -> 32 bit-words.
    if (blockIdx.x < 64) {
        const int lane = t & 31;
        const int base = blockIdx.x * 1024 + (t >> 5) * 256;   // 4 warps x 256
#pragma unroll
        for (int i = 0; i < 8; i++) {
            const float m = mask[base + i * 32 + lane];
            const unsigned bits = __ballot_sync(0xffffffffu, m != 0.0f);
            if (lane == 0) g_maskbits[(base + i * 32) >> 5] = bits;
        }
    }

    for (int i = t; i < 9 * 16; i += P1_T)
        w_s[i] = reinterpret_cast<const float4*>(kern)[i];

    unsigned long long acc2[9];
#pragma unroll
    for (int k = 0; k < 9; k++) acc2[k] = 0ull;

    const float4* in4 = reinterpret_cast<const float4*>(input) + (size_t)pixbase * 16;

#pragma unroll
    for (int half = 0; half < 2; half++) {
#pragma unroll
        for (int i = 0; i < 8; i++) {
            const int g  = i * P1_T + t;
            const int p  = g >> 3;
            const int c4 = g & 7;
            const float4* src = &in4[(size_t)p * 16 + half * 8 + c4];
            float4* dst = &in_s[p * 8 + (c4 ^ (p & 7))];
            const unsigned sdst = (unsigned)__cvta_generic_to_shared(dst);
            asm volatile("cp.async.cg.shared.global [%0], [%1], 16;\n"
                         :: "r"(sdst), "l"(src));
        }
        asm volatile("cp.async.commit_group;\n");
        asm volatile("cp.async.wait_group 0;\n" ::: "memory");
        __syncthreads();

#pragma unroll
        for (int c4 = 0; c4 < 8; c4++) {
            const ulonglong2 v = *reinterpret_cast<const ulonglong2*>(
                                     &in_s[t * 8 + (c4 ^ (t & 7))]);
#pragma unroll
            for (int k = 0; k < 9; k++) {
                const ulonglong2 wv = *reinterpret_cast<const ulonglong2*>(
                                          &w_s[k * 16 + half * 8 + c4]);
                acc2[k] = fma2(v.x, wv.x, acc2[k]);
                acc2[k] = fma2(v.y, wv.y, acc2[k]);
            }
        }
        __syncthreads();
    }

#pragma unroll
    for (int k = 0; k < 9; k++) {
        float lo, hi;
        asm("mov.b64 {%0, %1}, %2;" : "=f"(lo), "=f"(hi) : "l"(acc2[k]));
        g_P[k * PIX + pixbase + t] = lo + hi;
    }
}

// ---------------- Phase 2: bit-mask select-gather ----------------
constexpr int P2_T = 256;

__global__ __launch_bounds__(P2_T)
void dcn_phase2(const float* __restrict__ offset,   // [PIX,18]
                const float* __restrict__ bias,
                float* __restrict__ out)            // [PIX]
{
    __shared__ float    soff[P2_T * 18];   // 18 KB: offsets for this row
    __shared__ float    sP[9 * 256];       //  9 KB: base-tap P rows (plane k, row h+ky-2)
    __shared__ unsigned sbits[2048];       //  8 KB: whole bit-packed mask

    const int t = threadIdx.x;
    const int pixbase = blockIdx.x * P2_T;   // one image row per block
    const int b = pixbase >> 16;
    const int h = (pixbase >> 8) & 255;
    const int w = t;
    const float* Pb = g_P + (size_t)b * (Hc * Wc);

    {   // stage offsets: 1152 float4, coalesced
        const float4* off4 = reinterpret_cast<const float4*>(offset + (size_t)pixbase * 18);
        float4* soff4 = reinterpret_cast<float4*>(soff);
#pragma unroll
        for (int i = 0; i < 4; i++)
            soff4[i * P2_T + t] = off4[i * P2_T + t];
        if (t < 1152 - 4 * P2_T)
            soff4[4 * P2_T + t] = off4[4 * P2_T + t];
    }
    {   // stage bit-mask: 512 uint4, coalesced
        uint4* sb4 = reinterpret_cast<uint4*>(sbits);
        const uint4* gb4 = reinterpret_cast<const uint4*>(g_maskbits);
        sb4[t]         = gb4[t];
        sb4[t + P2_T]  = gb4[t + P2_T];
    }
#pragma unroll
    for (int k = 0; k < 9; k++) {        // base-tap P rows, coalesced
        const int row = h + k / 3 - 2;
        sP[k * 256 + t] = (row >= 0) ? g_P[k * PIX + b * (Hc * Wc) + row * Wc + t]
                                     : 0.0f;
    }
    __syncthreads();

    // bit test on UNPADDED coords (y,x in [0,255])
    auto mbit = [&](int y, int x) -> int {
        const unsigned word = sbits[y * 8 + (x >> 5)];
        return (word >> (x & 31)) & 1;
    };

    float acc = __ldg(bias);

#pragma unroll
    for (int k = 0; k < 9; k++) {
        const int ky = k / 3;
        const int kx = k - ky * 3;
        const int yb = h + ky - 1;
        const int xb = w + kx - 1;
        // joint padded-index-grid zeroing (reference semantics)
        const bool inb = (yb >= 0) & (yb < Hc) & (xb >= 0) & (xb < Wc);
        const int yi = inb ? yb : 0;
        const int xi = inb ? xb : 0;
        const bool base_ok = inb & (yb >= 1) & (xb >= 1);

        const float2 off2 = *reinterpret_cast<const float2*>(&soff[t * 18 + 2 * k]);

        // mask at base tap (padded coords; pad ring = 0)
        const int pm = base_ok ? mbit(yi - 1, xi - 1) : 0;

        // mask at offset point: floor, clip to padded range [0,257]
        int yo = (int)floorf((float)yi + off2.x);
        int xo = (int)floorf((float)xi + off2.y);
        yo = min(max(yo, 0), Hc + 1);
        xo = min(max(xo, 0), Wc + 1);
        const bool mo_ok = (yo >= 1) & (yo <= Hc) & (xo >= 1) & (xo <= Wc);
        const int pmo = mo_ok ? mbit(yo - 1, xo - 1) : 0;

        float val;
        if (pm != pmo) {
            // diff==1: sample padded input at clip(base+off)
            const float yf = fminf(fmaxf((float)yi + off2.x, 0.0f), 255.0f);
            const float xf = fminf(fmaxf((float)xi + off2.y, 0.0f), 255.0f);
            const int y0 = (int)floorf(yf);
            const int x0 = (int)floorf(xf);
            val = ((y0 >= 1) & (x0 >= 1))
                      ? Pb[k * PIX + (y0 - 1) * Wc + (x0 - 1)] : 0.0f;  // predicated gather
        } else {
            // diff==0: base tap; zero on the padded ring
            val = base_ok ? sP[k * 256 + (w + kx - 2)] : 0.0f;
        }
        acc += val;
    }

    out[pixbase + t] = acc;
}

} // namespace

extern "C" void kernel_launch(void* const* d_in, const int* in_sizes, int n_in,
                              void* d_out, int out_size)
{
    const float* input  = (const float*)d_in[0];   // [4,256,256,64]
    const float* mask   = (const float*)d_in[1];   // [1,256,256,1]
    const float* offset = (const float*)d_in[2];   // [4,256,256,18]
    const float* kern   = (const float*)d_in[3];   // [3,3,64,1]
    const float* bias   = (const float*)d_in[4];   // [1]
    float* out = (float*)d_out;

    dcn_phase1<<<PIX / P1_T, P1_T>>>(input, kern, mask);
    dcn_phase2<<<PIX / P2_T, P2_T>>>(offset, bias, out);
}

// round 8
// speedup vs baseline: 1.0345x; 1.0345x over previous
#include <cuda_runtime.h>
#include <cuda_bf16.h>

// DeformableConvLayer: B=4, H=W=256, C=64, K=3x3, UNITS=1.
//   Phase 1: P_k[pix] = <input[pix,:], kern[k,:]> (dense streaming contraction);
//            64 of its blocks also warp-ballot-pack the {0,1} mask into 8KB of bits.
//   Phase 2: out = bias + sum_k select(mask-diff, P_k@offset, P_k@base).
//            BRANCH-FREE: all 9 offset-path gathers issued unconditionally in one
//            wave (clamped addresses, value gated by SEL); both mask tests are
//            smem bit-tests; base values come from coalesced smem rows.

namespace {

constexpr int Hc = 256;
constexpr int Wc = 256;
constexpr int PIX = 4 * Hc * Wc;               // 262144

__device__ float    g_P[9 * PIX];              // 9.4 MB tap-plane scratch
__device__ unsigned g_maskbits[2048];          // 256x256 mask, 1 bit/px (8 KB)

__device__ __forceinline__ unsigned long long fma2(unsigned long long a,
                                                   unsigned long long b,
                                                   unsigned long long c)
{
    unsigned long long d;
    asm("fma.rn.f32x2 %0, %1, %2, %3;" : "=l"(d) : "l"(a), "l"(b), "l"(c));
    return d;
}

// ---------------- Phase 1: contraction + mask bit-pack ----------------
constexpr int P1_T = 128;

__global__ __launch_bounds__(P1_T)
void dcn_phase1(const float* __restrict__ input,   // [PIX, 64]
                const float* __restrict__ kern,    // [9, 64]
                const float* __restrict__ mask)    // [256,256]
{
    __shared__ float4 in_s[P1_T * 8];    // 16 KB, [pixel][c4 ^ (pixel&7)]
    __shared__ float4 w_s[9 * 16];

    const int t = threadIdx.x;
    const int pixbase = blockIdx.x * P1_T;

    // First 64 blocks also pack the mask: 1024 floats/block -> 32 bit-words.
    if (blockIdx.x < 64) {
        const int lane = t & 31;
        const int base = blockIdx.x * 1024 + (t >> 5) * 256;   // 4 warps x 256
#pragma unroll
        for (int i = 0; i < 8; i++) {
            const float m = mask[base + i * 32 + lane];
            const unsigned bits = __ballot_sync(0xffffffffu, m != 0.0f);
            if (lane == 0) g_maskbits[(base + i * 32) >> 5] = bits;
        }
    }

    for (int i = t; i < 9 * 16; i += P1_T)
        w_s[i] = reinterpret_cast<const float4*>(kern)[i];

    unsigned long long acc2[9];
#pragma unroll
    for (int k = 0; k < 9; k++) acc2[k] = 0ull;

    const float4* in4 = reinterpret_cast<const float4*>(input) + (size_t)pixbase * 16;

#pragma unroll
    for (int half = 0; half < 2; half++) {
#pragma unroll
        for (int i = 0; i < 8; i++) {
            const int g  = i * P1_T + t;
            const int p  = g >> 3;
            const int c4 = g & 7;
            const float4* src = &in4[(size_t)p * 16 + half * 8 + c4];
            float4* dst = &in_s[p * 8 + (c4 ^ (p & 7))];
            const unsigned sdst = (unsigned)__cvta_generic_to_shared(dst);
            asm volatile("cp.async.cg.shared.global [%0], [%1], 16;\n"
                         :: "r"(sdst), "l"(src));
        }
        asm volatile("cp.async.commit_group;\n");
        asm volatile("cp.async.wait_group 0;\n" ::: "memory");
        __syncthreads();

#pragma unroll
        for (int c4 = 0; c4 < 8; c4++) {
            const ulonglong2 v = *reinterpret_cast<const ulonglong2*>(
                                     &in_s[t * 8 + (c4 ^ (t & 7))]);
#pragma unroll
            for (int k = 0; k < 9; k++) {
                const ulonglong2 wv = *reinterpret_cast<const ulonglong2*>(
                                          &w_s[k * 16 + half * 8 + c4]);
                acc2[k] = fma2(v.x, wv.x, acc2[k]);
                acc2[k] = fma2(v.y, wv.y, acc2[k]);
            }
        }
        __syncthreads();
    }

#pragma unroll
    for (int k = 0; k < 9; k++) {
        float lo, hi;
        asm("mov.b64 {%0, %1}, %2;" : "=f"(lo), "=f"(hi) : "l"(acc2[k]));
        g_P[k * PIX + pixbase + t] = lo + hi;
    }
}

// ---------------- Phase 2: branch-free bit-mask select-gather ----------------
constexpr int P2_T = 256;

__global__ __launch_bounds__(P2_T)
void dcn_phase2(const float* __restrict__ offset,   // [PIX,18]
                const float* __restrict__ bias,
                float* __restrict__ out)            // [PIX]
{
    __shared__ float    soff[P2_T * 18];   // 18 KB offsets for this row
    __shared__ float    sP[9 * 256];       //  9 KB base-tap P rows (plane k, row h+ky-2)
    __shared__ unsigned sbits[2048];       //  8 KB whole bit-packed mask

    const int t = threadIdx.x;
    const int pixbase = blockIdx.x * P2_T;   // one image row per block
    const int b = pixbase >> 16;
    const int h = (pixbase >> 8) & 255;
    const int w = t;
    const float* Pb = g_P + (size_t)b * (Hc * Wc);

    {   // stage offsets: 1152 float4, coalesced
        const float4* off4 = reinterpret_cast<const float4*>(offset + (size_t)pixbase * 18);
        float4* soff4 = reinterpret_cast<float4*>(soff);
#pragma unroll
        for (int i = 0; i < 4; i++)
            soff4[i * P2_T + t] = off4[i * P2_T + t];
        if (t < 1152 - 4 * P2_T)
            soff4[4 * P2_T + t] = off4[4 * P2_T + t];
    }
    {   // stage bit-mask: 512 uint4, coalesced
        uint4* sb4 = reinterpret_cast<uint4*>(sbits);
        const uint4* gb4 = reinterpret_cast<const uint4*>(g_maskbits);
        sb4[t]        = gb4[t];
        sb4[t + P2_T] = gb4[t + P2_T];
    }
#pragma unroll
    for (int k = 0; k < 9; k++) {        // base-tap P rows, coalesced
        const int row = h + k / 3 - 2;
        sP[k * 256 + t] = (row >= 0) ? g_P[k * PIX + b * (Hc * Wc) + row * Wc + t]
                                     : 0.0f;
    }
    __syncthreads();

    // ---- wave 1: 9 UNCONDITIONAL offset-path gathers (clamped addresses) ----
    float Vo[9];
    bool  vvalid[9];
    int   yiv[9], xiv[9];
#pragma unroll
    for (int k = 0; k < 9; k++) {
        const int ky = k / 3;
        const int kx = k - ky * 3;
        const int yb = h + ky - 1;
        const int xb = w + kx - 1;
        const bool inb = (yb >= 0) & (yb < Hc) & (xb >= 0) & (xb < Wc);
        const int yi = inb ? yb : 0;
        const int xi = inb ? xb : 0;
        yiv[k] = yi;  xiv[k] = xi;

        const float2 off2 = *reinterpret_cast<const float2*>(&soff[t * 18 + 2 * k]);

        // diff==1 path: clip(yi+off, 0, 255), floor; padded sample -> valid iff >=1
        const float yf = fminf(fmaxf((float)yi + off2.x, 0.0f), 255.0f);
        const float xf = fminf(fmaxf((float)xi + off2.y, 0.0f), 255.0f);
        const int y0 = (int)floorf(yf);
        const int x0 = (int)floorf(xf);
        vvalid[k] = (y0 >= 1) & (x0 >= 1);
        const int idx = max(y0 - 1, 0) * Wc + max(x0 - 1, 0);   // always in range
        Vo[k] = Pb[k * PIX + idx];                               // batched LDG wave
    }

    // ---- branch-free mask tests + select + sum (smem/ALU only) ----
    float acc = __ldg(bias);
#pragma unroll
    for (int k = 0; k < 9; k++) {
        const int ky = k / 3;
        const int kx = k - ky * 3;
        const int yb = h + ky - 1;
        const int xb = w + kx - 1;
        const bool base_ok = (yb >= 1) & (yb < Hc) & (xb >= 1) & (xb < Wc);

        const float2 off2 = *reinterpret_cast<const float2*>(&soff[t * 18 + 2 * k]);

        // mask at base tap (padded coords; pad ring = 0)
        int pm = 0;
        {
            const int yy = yiv[k] - 1, xx = xiv[k] - 1;
            const unsigned word = sbits[max(yy, 0) * 8 + (max(xx, 0) >> 5)];
            pm = base_ok ? (int)((word >> (xx & 31)) & 1u) : 0;
        }
        // mask at offset point: floor, clip to padded [0,257]
        int yo = (int)floorf((float)yiv[k] + off2.x);
        int xo = (int)floorf((float)xiv[k] + off2.y);
        yo = min(max(yo, 0), Hc + 1);
        xo = min(max(xo, 0), Wc + 1);
        const bool mo_ok = (yo >= 1) & (yo <= Hc) & (xo >= 1) & (xo <= Wc);
        int pmo = 0;
        {
            const unsigned word = sbits[min(max(yo - 1, 0), 255) * 8
                                        + (min(max(xo - 1, 0), 255) >> 5)];
            pmo = mo_ok ? (int)((word >> ((xo - 1) & 31)) & 1u) : 0;
        }

        const float vo = vvalid[k] ? Vo[k] : 0.0f;
        const float vb = base_ok ? sP[k * 256 + (w + kx - 2)] : 0.0f;
        acc += (pm != pmo) ? vo : vb;        // SEL, no branch
    }

    out[pixbase + t] = acc;
}

} // namespace

extern "C" void kernel_launch(void* const* d_in, const int* in_sizes, int n_in,
                              void* d_out, int out_size)
{
    const float* input  = (const float*)d_in[0];   // [4,256,256,64]
    const float* mask   = (const float*)d_in[1];   // [1,256,256,1]
    const float* offset = (const float*)d_in[2];   // [4,256,256,18]
    const float* kern   = (const float*)d_in[3];   // [3,3,64,1]
    const float* bias   = (const float*)d_in[4];   // [1]
    float* out = (float*)d_out;

    dcn_phase1<<<PIX / P1_T, P1_T>>>(input, kern, mask);
    dcn_phase2<<<PIX / P2_T, P2_T>>>(offset, bias, out);
}

// round 9
// speedup vs baseline: 1.1715x; 1.1324x over previous
#include <cuda_runtime.h>
#include <cuda_bf16.h>

// DeformableConvLayer: B=4, H=W=256, C=64, K=3x3, UNITS=1.
//   Phase 1: P_k[pix] = <input[pix,:], kern[k,:]>  — dense streaming contraction,
//            DOUBLE-BUFFERED cp.async (both 16KB halves in flight; compute half0
//            overlaps the half1 stream). Packed f32x2 FMA.
//   Phase 2: out = bias + sum_k select(mask-diff, P_k@offset-coords, P_k@base-tap)
//            (exact R6 structure — proven fastest variant of the gather phase).

namespace {

constexpr int Hc = 256;
constexpr int Wc = 256;
constexpr int PIX = 4 * Hc * Wc;               // 262144

__device__ float g_P[9 * PIX];                 // 9.4 MB tap-plane scratch

__device__ __forceinline__ unsigned long long fma2(unsigned long long a,
                                                   unsigned long long b,
                                                   unsigned long long c)
{
    unsigned long long d;
    asm("fma.rn.f32x2 %0, %1, %2, %3;" : "=l"(d) : "l"(a), "l"(b), "l"(c));
    return d;
}

// ---------------- Phase 1: double-buffered contraction ----------------
constexpr int P1_T = 128;

__global__ __launch_bounds__(P1_T)
void dcn_phase1(const float* __restrict__ input,   // [PIX, 64]
                const float* __restrict__ kern)    // [9, 64]
{
    __shared__ float4 in_s[2][P1_T * 8];  // 2 x 16 KB, [pixel][c4 ^ (pixel&7)]
    __shared__ float4 w_s[9 * 16];        // 2.3 KB

    const int t = threadIdx.x;
    const int pixbase = blockIdx.x * P1_T;

    for (int i = t; i < 9 * 16; i += P1_T)
        w_s[i] = reinterpret_cast<const float4*>(kern)[i];

    const float4* in4 = reinterpret_cast<const float4*>(input) + (size_t)pixbase * 16;

    // Issue BOTH halves immediately (two cp.async groups in flight).
#pragma unroll
    for (int half = 0; half < 2; half++) {
#pragma unroll
        for (int i = 0; i < 8; i++) {
            const int g  = i * P1_T + t;
            const int p  = g >> 3;
            const int c4 = g & 7;
            const float4* src = &in4[(size_t)p * 16 + half * 8 + c4];
            float4* dst = &in_s[half][p * 8 + (c4 ^ (p & 7))];
            const unsigned sdst = (unsigned)__cvta_generic_to_shared(dst);
            asm volatile("cp.async.cg.shared.global [%0], [%1], 16;\n"
                         :: "r"(sdst), "l"(src));
        }
        asm volatile("cp.async.commit_group;\n");
    }

    unsigned long long acc2[9];
#pragma unroll
    for (int k = 0; k < 9; k++) acc2[k] = 0ull;

    // half 0 ready while half 1 still streams
    asm volatile("cp.async.wait_group 1;\n" ::: "memory");
    __syncthreads();
#pragma unroll
    for (int c4 = 0; c4 < 8; c4++) {
        const ulonglong2 v = *reinterpret_cast<const ulonglong2*>(
                                 &in_s[0][t * 8 + (c4 ^ (t & 7))]);
#pragma unroll
        for (int k = 0; k < 9; k++) {
            const ulonglong2 wv = *reinterpret_cast<const ulonglong2*>(&w_s[k * 16 + c4]);
            acc2[k] = fma2(v.x, wv.x, acc2[k]);
            acc2[k] = fma2(v.y, wv.y, acc2[k]);
        }
    }

    asm volatile("cp.async.wait_group 0;\n" ::: "memory");
    __syncthreads();
#pragma unroll
    for (int c4 = 0; c4 < 8; c4++) {
        const ulonglong2 v = *reinterpret_cast<const ulonglong2*>(
                                 &in_s[1][t * 8 + (c4 ^ (t & 7))]);
#pragma unroll
        for (int k = 0; k < 9; k++) {
            const ulonglong2 wv = *reinterpret_cast<const ulonglong2*>(&w_s[k * 16 + 8 + c4]);
            acc2[k] = fma2(v.x, wv.x, acc2[k]);
            acc2[k] = fma2(v.y, wv.y, acc2[k]);
        }
    }

#pragma unroll
    for (int k = 0; k < 9; k++) {
        float lo, hi;
        asm("mov.b64 {%0, %1}, %2;" : "=f"(lo), "=f"(hi) : "l"(acc2[k]));
        g_P[k * PIX + pixbase + t] = lo + hi;
    }
}

// ---------------- Phase 2: one-wave deformable select-gather (R6) ----------------
constexpr int P2_T = 256;

__global__ __launch_bounds__(P2_T)
void dcn_phase2(const float* __restrict__ mask,     // [256,256]
                const float* __restrict__ offset,   // [PIX,18]
                const float* __restrict__ bias,
                float* __restrict__ out)            // [PIX]
{
    __shared__ float soff[P2_T * 18];    // 18 KB offsets for this row
    __shared__ float smask[3 * 256];     // base-mask rows h-2..h
    __shared__ float sP[9 * 256];        // base-tap P rows: plane k, row h+ky-2

    const int t = threadIdx.x;
    const int pixbase = blockIdx.x * P2_T;   // one image row per block
    const int b = pixbase >> 16;
    const int h = (pixbase >> 8) & 255;
    const int w = t;
    const float* Pb = g_P + (size_t)b * (Hc * Wc);

    {   // stage offsets: 1152 float4, coalesced
        const float4* off4 = reinterpret_cast<const float4*>(offset + (size_t)pixbase * 18);
        float4* soff4 = reinterpret_cast<float4*>(soff);
#pragma unroll
        for (int i = 0; i < 4; i++)
            soff4[i * P2_T + t] = off4[i * P2_T + t];
        if (t < 1152 - 4 * P2_T)
            soff4[4 * P2_T + t] = off4[4 * P2_T + t];
    }
#pragma unroll
    for (int r = 0; r < 3; r++) {
        const int row = h - 2 + r;
        smask[r * 256 + t] = (row >= 0) ? mask[row * Wc + t] : 0.0f;
    }
#pragma unroll
    for (int k = 0; k < 9; k++) {        // base-tap P rows (coalesced)
        const int row = h + k / 3 - 2;
        sP[k * 256 + t] = (row >= 0) ? g_P[k * PIX + b * (Hc * Wc) + row * Wc + t]
                                     : 0.0f;
    }
    __syncthreads();

    // ---- single wave: 9 offset-path P gathers + 9 offset-mask gathers ----
    float Vo[9], pmoff[9];
#pragma unroll
    for (int k = 0; k < 9; k++) {
        const int ky = k / 3;
        const int kx = k - ky * 3;
        const int yb = h + ky - 1;
        const int xb = w + kx - 1;
        const bool inb = (yb >= 0) & (yb < Hc) & (xb >= 0) & (xb < Wc);
        const int yi = inb ? yb : 0;
        const int xi = inb ? xb : 0;

        const float2 off2 = *reinterpret_cast<const float2*>(&soff[t * 18 + 2 * k]);

        // offset-path final coords (diff==1 case): clip(yi+off, 0, 255), floor
        const float yf = fminf(fmaxf((float)yi + off2.x, 0.0f), 255.0f);
        const float xf = fminf(fmaxf((float)xi + off2.y, 0.0f), 255.0f);
        const int y0 = (int)floorf(yf);
        const int x0 = (int)floorf(xf);
        Vo[k] = ((y0 >= 1) & (x0 >= 1))
                    ? Pb[k * PIX + (y0 - 1) * Wc + (x0 - 1)] : 0.0f;

        // mask at offset point (padded coords, floor + clip to [0,257])
        int yo = (int)floorf((float)yi + off2.x);
        int xo = (int)floorf((float)xi + off2.y);
        yo = min(max(yo, 0), Hc + 1);
        xo = min(max(xo, 0), Wc + 1);
        pmoff[k] = ((yo >= 1) & (yo <= Hc) & (xo >= 1) & (xo <= Wc))
                       ? mask[(yo - 1) * Wc + (xo - 1)] : 0.0f;
    }

    // ---- select + sum (smem-only consumers) ----
    float acc = __ldg(bias);
#pragma unroll
    for (int k = 0; k < 9; k++) {
        const int ky = k / 3;
        const int kx = k - ky * 3;
        const int yb = h + ky - 1;
        const int xb = w + kx - 1;
        const bool base_ok = (yb >= 1) & (yb < Hc) & (xb >= 1) & (xb < Wc);
        const float pmask = base_ok ? smask[ky * 256 + (w + kx - 2)] : 0.0f;
        const float Vb    = base_ok ? sP[k * 256 + (w + kx - 2)] : 0.0f;
        acc += (pmask != pmoff[k]) ? Vo[k] : Vb;
    }

    out[pixbase + t] = acc;
}

} // namespace

extern "C" void kernel_launch(void* const* d_in, const int* in_sizes, int n_in,
                              void* d_out, int out_size)
{
    const float* input  = (const float*)d_in[0];   // [4,256,256,64]
    const float* mask   = (const float*)d_in[1];   // [1,256,256,1]
    const float* offset = (const float*)d_in[2];   // [4,256,256,18]
    const float* kern   = (const float*)d_in[3];   // [3,3,64,1]
    const float* bias   = (const float*)d_in[4];   // [1]
    float* out = (float*)d_out;

    dcn_phase1<<<PIX / P1_T, P1_T>>>(input, kern);
    dcn_phase2<<<PIX / P2_T, P2_T>>>(mask, offset, bias, out);
}